// round 1
// baseline (speedup 1.0000x reference)
#include <cuda_runtime.h>

#define NB 4
#define NN 2048
#define NF 128
#define RT 64      // rows per attention block
#define PS 132     // p_s row stride (floats), padded

// Scratch (no cudaMalloc allowed)
__device__ float g_Wh[NB * NN * NF];
__device__ float g_f1[NB * NN];
__device__ float g_f2[NB * NN];

// ---------------------------------------------------------------------------
// Kernel 1: Wh = h @ W ; f1 = Wh @ a1 ; f2 = Wh @ a2
// grid 256 blocks x 256 threads, 32 rows per block, full K=128 in smem.
// ---------------------------------------------------------------------------
__global__ void k_gemm1(const float* __restrict__ h,
                        const float* __restrict__ W,
                        const float* __restrict__ a) {
    extern __shared__ float sm1[];
    float* hs = sm1;              // [32][128]
    float* Ws = sm1 + 32 * 128;   // [128][128]
    int tid = threadIdx.x;
    int m0 = blockIdx.x * 32;     // row in flattened [B*N]

    // load h tile: 1024 float4
    {
        const float4* src = reinterpret_cast<const float4*>(h + (size_t)m0 * NF);
        float4* dst = reinterpret_cast<float4*>(hs);
        #pragma unroll
        for (int it = 0; it < 4; it++) dst[tid + it * 256] = src[tid + it * 256];
    }
    // load W: 4096 float4
    {
        const float4* src = reinterpret_cast<const float4*>(W);
        float4* dst = reinterpret_cast<float4*>(Ws);
        #pragma unroll
        for (int it = 0; it < 16; it++) dst[tid + it * 256] = src[tid + it * 256];
    }
    __syncthreads();

    int ty = tid >> 5;   // 0..7  -> rows ty*4..ty*4+3
    int tx = tid & 31;   // 0..31 -> cols tx*4..tx*4+3
    float acc[4][4] = {};

    #pragma unroll 4
    for (int k = 0; k < 128; k++) {
        float4 bv = *reinterpret_cast<const float4*>(&Ws[k * 128 + tx * 4]);
        #pragma unroll
        for (int mi = 0; mi < 4; mi++) {
            float av = hs[(ty * 4 + mi) * 128 + k];   // broadcast
            acc[mi][0] += av * bv.x;
            acc[mi][1] += av * bv.y;
            acc[mi][2] += av * bv.z;
            acc[mi][3] += av * bv.w;
        }
    }

    // epilogue: f1/f2 via warp reduction (warp owns 4 full rows)
    float a1v[4], a2v[4];
    #pragma unroll
    for (int ni = 0; ni < 4; ni++) {
        a1v[ni] = a[tx * 4 + ni];
        a2v[ni] = a[NF + tx * 4 + ni];
    }
    #pragma unroll
    for (int mi = 0; mi < 4; mi++) {
        float p1 = acc[mi][0] * a1v[0] + acc[mi][1] * a1v[1]
                 + acc[mi][2] * a1v[2] + acc[mi][3] * a1v[3];
        float p2 = acc[mi][0] * a2v[0] + acc[mi][1] * a2v[1]
                 + acc[mi][2] * a2v[2] + acc[mi][3] * a2v[3];
        #pragma unroll
        for (int off = 16; off > 0; off >>= 1) {
            p1 += __shfl_xor_sync(0xffffffffu, p1, off);
            p2 += __shfl_xor_sync(0xffffffffu, p2, off);
        }
        if (tx == 0) {
            g_f1[m0 + ty * 4 + mi] = p1;
            g_f2[m0 + ty * 4 + mi] = p2;
        }
        float4 o = make_float4(acc[mi][0], acc[mi][1], acc[mi][2], acc[mi][3]);
        *reinterpret_cast<float4*>(&g_Wh[(size_t)(m0 + ty * 4 + mi) * NF + tx * 4]) = o;
    }
}

// ---------------------------------------------------------------------------
// Kernel 2: fused masked-softmax attention + P@Wh
// grid (32, 4) blocks x 512 threads; 64 output rows per block; one wave.
// Single-pass softmax (no max subtraction; scores bounded ~11, fp32-safe).
// ---------------------------------------------------------------------------
__global__ void k_attn(const int* __restrict__ adj, float* __restrict__ out) {
    extern __shared__ float sm2[];
    float* Whs  = sm2;                 // [128][128]  Wh j-tile
    float* p_s  = sm2 + 128 * 128;     // [64][PS]    attention weights tile
    float* f1s  = p_s + RT * PS;       // [64]
    float* f2s  = f1s + RT;            // [128]
    float* dinv = f2s + 128;           // [64]

    int tid  = threadIdx.x;
    int b    = blockIdx.y;
    int row0 = blockIdx.x * RT;
    const float* Whb = g_Wh + (size_t)b * NN * NF;

    if (tid < RT) f1s[tid] = g_f1[b * NN + row0 + tid];

    int tr = tid >> 5;            // 0..15 -> rows tr*4..tr*4+3
    int tc = tid & 31;            // 0..31 -> cols tc*4..tc*4+3
    int pr  = tid >> 3;           // phase-A row 0..63
    int pj0 = (tid & 7) * 16;     // phase-A j start within tile

    float acc[4][4] = {};
    float dacc = 0.0f;

    for (int t = 0; t < 16; t++) {
        int j0 = t * 128;
        __syncthreads();  // previous tile fully consumed (also orders f1s on t=0)

        // load Wh tile (rows j0..j0+127, all 128 cols): 4096 float4
        {
            const float4* src = reinterpret_cast<const float4*>(Whb) + (size_t)j0 * 32;
            float4* dst = reinterpret_cast<float4*>(Whs);
            #pragma unroll
            for (int it = 0; it < 8; it++) dst[tid + it * 512] = src[tid + it * 512];
        }
        if (tid < 128) f2s[tid] = g_f2[b * NN + j0 + tid];
        __syncthreads();

        // phase A: p[r][j] = adj ? exp(lrelu(f1_r + f2_j)) : 0
        {
            float f1v = f1s[pr];
            const int4* arow = reinterpret_cast<const int4*>(
                adj + (size_t)(row0 + pr) * NN + j0 + pj0);
            float* prow = &p_s[pr * PS + pj0];
            #pragma unroll
            for (int q = 0; q < 4; q++) {
                int4 av = arow[q];
                float s0 = f1v + f2s[pj0 + q * 4 + 0]; s0 = s0 > 0.f ? s0 : 0.2f * s0;
                float s1 = f1v + f2s[pj0 + q * 4 + 1]; s1 = s1 > 0.f ? s1 : 0.2f * s1;
                float s2 = f1v + f2s[pj0 + q * 4 + 2]; s2 = s2 > 0.f ? s2 : 0.2f * s2;
                float s3 = f1v + f2s[pj0 + q * 4 + 3]; s3 = s3 > 0.f ? s3 : 0.2f * s3;
                prow[q * 4 + 0] = (av.x > 0) ? __expf(s0) : 0.0f;
                prow[q * 4 + 1] = (av.y > 0) ? __expf(s1) : 0.0f;
                prow[q * 4 + 2] = (av.z > 0) ? __expf(s2) : 0.0f;
                prow[q * 4 + 3] = (av.w > 0) ? __expf(s3) : 0.0f;
            }
        }
        __syncthreads();

        // phase B: acc += P_tile @ Wh_tile  (register tile 4x4, FFMA-bound)
        {
            const float* q0 = &p_s[(tr * 4 + 0) * PS];
            const float* q1 = &p_s[(tr * 4 + 1) * PS];
            const float* q2 = &p_s[(tr * 4 + 2) * PS];
            const float* q3 = &p_s[(tr * 4 + 3) * PS];
            #pragma unroll 8
            for (int j = 0; j < 128; j++) {
                float4 bv = *reinterpret_cast<const float4*>(&Whs[j * 128 + tc * 4]);
                float a0 = q0[j], a1 = q1[j], a2 = q2[j], a3 = q3[j];
                acc[0][0] += a0 * bv.x; acc[0][1] += a0 * bv.y;
                acc[0][2] += a0 * bv.z; acc[0][3] += a0 * bv.w;
                acc[1][0] += a1 * bv.x; acc[1][1] += a1 * bv.y;
                acc[1][2] += a1 * bv.z; acc[1][3] += a1 * bv.w;
                acc[2][0] += a2 * bv.x; acc[2][1] += a2 * bv.y;
                acc[2][2] += a2 * bv.z; acc[2][3] += a2 * bv.w;
                acc[3][0] += a3 * bv.x; acc[3][1] += a3 * bv.y;
                acc[3][2] += a3 * bv.z; acc[3][3] += a3 * bv.w;
            }
        }

        // denominator partials (2 warps; p_s stays valid until next phase A)
        if (tid < RT) {
            const float* prw = &p_s[tid * PS];
            float s = 0.f;
            #pragma unroll 8
            for (int j = 0; j < 128; j++) s += prw[j];
            dacc += s;
        }
    }

    if (tid < RT) dinv[tid] = 1.0f / dacc;
    __syncthreads();

    float* ob = out + ((size_t)b * NN + row0) * NF;
    #pragma unroll
    for (int mi = 0; mi < 4; mi++) {
        float s = dinv[tr * 4 + mi];
        float4 o = make_float4(acc[mi][0] * s, acc[mi][1] * s,
                               acc[mi][2] * s, acc[mi][3] * s);
        *reinterpret_cast<float4*>(&ob[(tr * 4 + mi) * NF + tc * 4]) = o;
    }
}

// ---------------------------------------------------------------------------
extern "C" void kernel_launch(void* const* d_in, const int* in_sizes, int n_in,
                              void* d_out, int out_size) {
    const float* h   = (const float*)d_in[0];
    const int*   adj = (const int*)d_in[1];
    const float* W   = (const float*)d_in[2];
    const float* a   = (const float*)d_in[3];
    float* out = (float*)d_out;

    int sm1 = (32 * 128 + 128 * 128) * 4;                          // 81920 B
    int sm2 = (128 * 128 + RT * PS + RT + 128 + RT) * 4;           // 100352 B
    cudaFuncSetAttribute(k_gemm1, cudaFuncAttributeMaxDynamicSharedMemorySize, sm1);
    cudaFuncSetAttribute(k_attn,  cudaFuncAttributeMaxDynamicSharedMemorySize, sm2);

    k_gemm1<<<(NB * NN) / 32, 256, sm1>>>(h, W, a);
    k_attn<<<dim3(NN / RT, NB), 512, sm2>>>(adj, out);
}

// round 3
// speedup vs baseline: 2.2060x; 2.2060x over previous
#include <cuda_runtime.h>
#include <cuda_bf16.h>
#include <cstdint>

#define NB 4
#define NN 2048
#define NF 128
#define RT 64        // rows per attention block (M)
#define KT 64        // j per K tile
#define NTILE (NN / KT)

// ---- scratch (no cudaMalloc allowed) ----
__device__ __nv_bfloat16 g_WhT_h[NB * NF * NN];   // [b][o][n] hi
__device__ __nv_bfloat16 g_WhT_l[NB * NF * NN];   // [b][o][n] lo
__device__ float    g_f1[NB * NN];
__device__ float    g_f2[NB * NN];
__device__ uint32_t g_mask[NN * (NN / 32)];       // [row][64 words]

// ---------------------------------------------------------------------------
__device__ __forceinline__ uint32_t smem_u32(const void* p) {
    uint32_t a;
    asm("{ .reg .u64 t; cvta.to.shared.u64 t, %1; cvt.u32.u64 %0, t; }" : "=r"(a) : "l"(p));
    return a;
}
__device__ __forceinline__ uint32_t swz(uint32_t x) { return x ^ ((x >> 3) & 0x70); }

__device__ __forceinline__ uint32_t pk(float a, float b) {   // lo<-a, hi<-b
    uint32_t r;
    asm("cvt.rn.bf16x2.f32 %0, %1, %2;" : "=r"(r) : "f"(b), "f"(a));
    return r;
}
__device__ __forceinline__ void ldm4(uint32_t* r, uint32_t addr) {
    asm volatile("ldmatrix.sync.aligned.m8n8.x4.shared.b16 {%0,%1,%2,%3}, [%4];"
        : "=r"(r[0]), "=r"(r[1]), "=r"(r[2]), "=r"(r[3]) : "r"(addr));
}
__device__ __forceinline__ void mma16816(float* d, const uint32_t* a, const uint32_t* b) {
    asm volatile("mma.sync.aligned.m16n8k16.row.col.f32.bf16.bf16.f32 "
        "{%0,%1,%2,%3}, {%4,%5,%6,%7}, {%8,%9}, {%0,%1,%2,%3};"
        : "+f"(d[0]), "+f"(d[1]), "+f"(d[2]), "+f"(d[3])
        : "r"(a[0]), "r"(a[1]), "r"(a[2]), "r"(a[3]), "r"(b[0]), "r"(b[1]));
}
#define CPA(dst, src) asm volatile("cp.async.cg.shared.global [%0], [%1], 16;" :: "r"(dst), "l"(src) : "memory")
#define CPC()   asm volatile("cp.async.commit_group;" ::: "memory")
#define CPW(n)  asm volatile("cp.async.wait_group %0;" :: "n"(n) : "memory")

// ---------------------------------------------------------------------------
// Kernel 0: pack adjacency to bitmask
// ---------------------------------------------------------------------------
__global__ void k_pack(const int* __restrict__ adj) {
    int w = blockIdx.x * 8 + (threadIdx.x >> 5);     // word index
    int lane = threadIdx.x & 31;
    int v = adj[(size_t)w * 32 + lane];
    uint32_t m = __ballot_sync(0xffffffffu, v > 0);
    if (lane == 0) g_mask[w] = m;
}

// ---------------------------------------------------------------------------
// Kernel 1: Wh = h@W ; f1 = Wh@a1 ; f2 = Wh@a2 ; WhT (bf16 hi/lo) to global
// ---------------------------------------------------------------------------
__global__ void k_gemm1(const float* __restrict__ h,
                        const float* __restrict__ W,
                        const float* __restrict__ a) {
    extern __shared__ float sm1[];
    float* hs = sm1;
    float* Ws = sm1 + 32 * 128;
    int tid = threadIdx.x;
    int m0 = blockIdx.x * 32;

    {
        const float4* src = reinterpret_cast<const float4*>(h + (size_t)m0 * NF);
        float4* dst = reinterpret_cast<float4*>(hs);
        #pragma unroll
        for (int it = 0; it < 4; it++) dst[tid + it * 256] = src[tid + it * 256];
    }
    {
        const float4* src = reinterpret_cast<const float4*>(W);
        float4* dst = reinterpret_cast<float4*>(Ws);
        #pragma unroll
        for (int it = 0; it < 16; it++) dst[tid + it * 256] = src[tid + it * 256];
    }
    __syncthreads();

    int ty = tid >> 5;
    int tx = tid & 31;
    float acc[4][4] = {};

    #pragma unroll 4
    for (int k = 0; k < 128; k++) {
        float4 bv = *reinterpret_cast<const float4*>(&Ws[k * 128 + tx * 4]);
        #pragma unroll
        for (int mi = 0; mi < 4; mi++) {
            float av = hs[(ty * 4 + mi) * 128 + k];
            acc[mi][0] += av * bv.x;
            acc[mi][1] += av * bv.y;
            acc[mi][2] += av * bv.z;
            acc[mi][3] += av * bv.w;
        }
    }

    float a1v[4], a2v[4];
    #pragma unroll
    for (int ni = 0; ni < 4; ni++) {
        a1v[ni] = a[tx * 4 + ni];
        a2v[ni] = a[NF + tx * 4 + ni];
    }
    #pragma unroll
    for (int mi = 0; mi < 4; mi++) {
        float p1 = acc[mi][0] * a1v[0] + acc[mi][1] * a1v[1]
                 + acc[mi][2] * a1v[2] + acc[mi][3] * a1v[3];
        float p2 = acc[mi][0] * a2v[0] + acc[mi][1] * a2v[1]
                 + acc[mi][2] * a2v[2] + acc[mi][3] * a2v[3];
        #pragma unroll
        for (int off = 16; off > 0; off >>= 1) {
            p1 += __shfl_xor_sync(0xffffffffu, p1, off);
            p2 += __shfl_xor_sync(0xffffffffu, p2, off);
        }
        if (tx == 0) {
            g_f1[m0 + ty * 4 + mi] = p1;
            g_f2[m0 + ty * 4 + mi] = p2;
        }
    }

    // transposed bf16 hi/lo: WhT[b][o][m]
    int bb = m0 >> 11;
    int ml = (m0 & 2047) + ty * 4;
    #pragma unroll
    for (int ni = 0; ni < 4; ni++) {
        int o = tx * 4 + ni;
        float v0 = acc[0][ni], v1 = acc[1][ni], v2 = acc[2][ni], v3 = acc[3][ni];
        uint32_t hA = pk(v0, v1);
        uint32_t hB = pk(v2, v3);
        float r0 = v0 - __uint_as_float(hA << 16);
        float r1 = v1 - __uint_as_float(hA & 0xffff0000u);
        float r2 = v2 - __uint_as_float(hB << 16);
        float r3 = v3 - __uint_as_float(hB & 0xffff0000u);
        size_t base = (size_t)(bb * 128 + o) * 1024 + (ml >> 1);
        uint32_t* dh = reinterpret_cast<uint32_t*>(g_WhT_h) + base;
        uint32_t* dl = reinterpret_cast<uint32_t*>(g_WhT_l) + base;
        dh[0] = hA; dh[1] = hB;
        dl[0] = pk(r0, r1); dl[1] = pk(r2, r3);
    }
}

// ---------------------------------------------------------------------------
// Kernel 2: fused masked-softmax attention + P@Wh via mma.sync (bf16 3-term)
// grid (32, 4) x 512 threads; 64 rows x 128 cols per block.
// ---------------------------------------------------------------------------
// smem byte offsets
#define AS_OFF 0u           // P tile: hi 8KB @0, lo 8KB @8192
#define BT_OFF 16384u       // 2 bufs x (hi 16KB + lo 16KB)
#define F2_OFF 81920u       // 2048 floats
#define MS_OFF 90112u       // 64 rows x 64 words
#define DI_OFF 106496u      // 64 floats
#define SMEM_TOT (106496 + 256)

__global__ void __launch_bounds__(512, 1)
k_attn(float* __restrict__ out) {
    extern __shared__ char smemA[];
    uint32_t sb = smem_u32(smemA);
    int tid = threadIdx.x;
    int wid = tid >> 5;
    int lane = tid & 31;
    int b = blockIdx.y;
    int row0 = blockIdx.x * RT;

    float* f2s = reinterpret_cast<float*>(smemA + F2_OFF);
    uint32_t* ms = reinterpret_cast<uint32_t*>(smemA + MS_OFF);
    float* di = reinterpret_cast<float*>(smemA + DI_OFF);

    // ---- preload f2 (whole row, 8KB) and mask rows (16KB) ----
    {
        const float4* s4 = reinterpret_cast<const float4*>(g_f2 + b * NN);
        reinterpret_cast<float4*>(f2s)[tid] = s4[tid];
        const uint4* m4 = reinterpret_cast<const uint4*>(g_mask + row0 * 64);
        uint4* d4 = reinterpret_cast<uint4*>(ms);
        d4[tid * 2 + 0] = m4[tid * 2 + 0];
        d4[tid * 2 + 1] = m4[tid * 2 + 1];
    }

    // ---- per-thread phase-A constants ----
    int r = tid >> 3;                 // 0..63
    int c8 = (tid & 7) * 8;           // j offset within tile
    float f1v = g_f1[b * NN + row0 + r];
    uint32_t aStHi = sb + AS_OFF + swz((uint32_t)(r * 128 + (tid & 7) * 16));
    uint32_t aStLo = aStHi + 8192u;

    // ---- MMA fragment addresses ----
    int wr = wid >> 2, wc = wid & 3;
    uint32_t aRowOff = (uint32_t)((wr * 16 + (lane & 7) + ((lane >> 3) & 1) * 8) * 128
                                  + (((lane >> 4) & 1) * 8) * 2);
    int bRow = wc * 32 + ((lane >> 4) & 1) * 8 + (lane & 7);
    uint32_t bColOff = (uint32_t)(((lane >> 3) & 1) * 16);
    uint32_t bBase = (uint32_t)(bRow * 128) + bColOff;

    // cp.async per-thread mapping (4 x 16B)
    uint32_t cpDst[4];
    const __nv_bfloat16* cpSrcBase[4];
    #pragma unroll
    for (int k = 0; k < 4; k++) {
        int s = tid + k * 512;
        int split = s >> 10, s2 = s & 1023;
        int o = s2 >> 3, seg = s2 & 7;
        cpDst[k] = (uint32_t)split * 16384u + swz((uint32_t)(o * 128 + seg * 16));
        cpSrcBase[k] = (split ? g_WhT_l : g_WhT_h) + ((size_t)(b * 128 + o) * NN + seg * 8);
    }

    float acc[4][4] = {};   // 4 n-frags x 4 regs
    float dacc = 0.0f;

    // prologue: B tile 0
    {
        uint32_t dbase = sb + BT_OFF;
        #pragma unroll
        for (int k = 0; k < 4; k++) CPA(dbase + cpDst[k], cpSrcBase[k]);
        CPC();
    }

    for (int t = 0; t < NTILE; t++) {
        int j0 = t * KT;
        uint32_t bufB = sb + BT_OFF + (uint32_t)(t & 1) * 32768u;

        __syncthreads();   // everyone done with MMA(t-1): safe to rewrite As, issue into bufB(t+1)

        if (t + 1 < NTILE) {
            uint32_t dbase = sb + BT_OFF + (uint32_t)((t + 1) & 1) * 32768u;
            #pragma unroll
            for (int k = 0; k < 4; k++) CPA(dbase + cpDst[k], cpSrcBase[k] + (j0 + KT));
            CPC();
        }

        // ---- phase A: P tile (bf16 hi/lo) + row-sum partials ----
        {
            uint32_t mw = ms[r * 64 + t * 2 + (c8 >> 5)];
            uint32_t bits = mw >> (c8 & 31);
            const float4* fv4 = reinterpret_cast<const float4*>(f2s + j0 + c8);
            float4 fa = fv4[0], fb = fv4[1];
            float p0, p1, p2, p3, p4, p5, p6, p7;
            {
                float s0 = f1v + fa.x; s0 = s0 > 0.f ? s0 : 0.2f * s0;
                float s1 = f1v + fa.y; s1 = s1 > 0.f ? s1 : 0.2f * s1;
                float s2 = f1v + fa.z; s2 = s2 > 0.f ? s2 : 0.2f * s2;
                float s3 = f1v + fa.w; s3 = s3 > 0.f ? s3 : 0.2f * s3;
                p0 = (bits & 1u)   ? __expf(s0) : 0.0f;
                p1 = (bits & 2u)   ? __expf(s1) : 0.0f;
                p2 = (bits & 4u)   ? __expf(s2) : 0.0f;
                p3 = (bits & 8u)   ? __expf(s3) : 0.0f;
                float s4 = f1v + fb.x; s4 = s4 > 0.f ? s4 : 0.2f * s4;
                float s5 = f1v + fb.y; s5 = s5 > 0.f ? s5 : 0.2f * s5;
                float s6 = f1v + fb.z; s6 = s6 > 0.f ? s6 : 0.2f * s6;
                float s7 = f1v + fb.w; s7 = s7 > 0.f ? s7 : 0.2f * s7;
                p4 = (bits & 16u)  ? __expf(s4) : 0.0f;
                p5 = (bits & 32u)  ? __expf(s5) : 0.0f;
                p6 = (bits & 64u)  ? __expf(s6) : 0.0f;
                p7 = (bits & 128u) ? __expf(s7) : 0.0f;
            }
            dacc += ((p0 + p1) + (p2 + p3)) + ((p4 + p5) + (p6 + p7));
            uint32_t h0 = pk(p0, p1), h1 = pk(p2, p3), h2 = pk(p4, p5), h3 = pk(p6, p7);
            float q0 = p0 - __uint_as_float(h0 << 16);
            float q1 = p1 - __uint_as_float(h0 & 0xffff0000u);
            float q2 = p2 - __uint_as_float(h1 << 16);
            float q3 = p3 - __uint_as_float(h1 & 0xffff0000u);
            float q4 = p4 - __uint_as_float(h2 << 16);
            float q5 = p5 - __uint_as_float(h2 & 0xffff0000u);
            float q6 = p6 - __uint_as_float(h3 << 16);
            float q7 = p7 - __uint_as_float(h3 & 0xffff0000u);
            *reinterpret_cast<uint4*>(smemA + (aStHi - sb)) = make_uint4(h0, h1, h2, h3);
            *reinterpret_cast<uint4*>(smemA + (aStLo - sb)) =
                make_uint4(pk(q0, q1), pk(q2, q3), pk(q4, q5), pk(q6, q7));
        }

        if (t + 1 < NTILE) { CPW(1); } else { CPW(0); }
        __syncthreads();   // As complete + B(t) landed everywhere

        // ---- MMA phase: 4 ksteps x (3 terms x 4 nfrags) ----
        #pragma unroll
        for (int ks = 0; ks < 4; ks++) {
            uint32_t ah[4], al[4], bh[8], bl[8];
            uint32_t aAddr = sb + AS_OFF + swz(aRowOff + 32u * ks);
            ldm4(ah, aAddr);
            ldm4(al, aAddr + 8192u);
            uint32_t b0 = bufB + swz(bBase + 32u * ks);
            uint32_t b1 = bufB + swz(bBase + 2048u + 32u * ks);   // +16 rows of o (2c=2)
            ldm4(bh + 0, b0);
            ldm4(bh + 4, b1);
            ldm4(bl + 0, b0 + 16384u);
            ldm4(bl + 4, b1 + 16384u);
            #pragma unroll
            for (int nb = 0; nb < 4; nb++) {
                mma16816(acc[nb], ah, bh + nb * 2);
                mma16816(acc[nb], ah, bl + nb * 2);
                mma16816(acc[nb], al, bh + nb * 2);
            }
        }
    }

    // ---- softmax denominator ----
    dacc += __shfl_xor_sync(0xffffffffu, dacc, 1);
    dacc += __shfl_xor_sync(0xffffffffu, dacc, 2);
    dacc += __shfl_xor_sync(0xffffffffu, dacc, 4);
    if ((lane & 7) == 0) di[wid * 4 + (lane >> 3)] = 1.0f / dacc;
    __syncthreads();

    // ---- epilogue: scale + store ----
    int rA = wr * 16 + (lane >> 2);
    float d0 = di[rA];
    float d1 = di[rA + 8];
    float* orow0 = out + ((size_t)(b * NN + row0 + rA)) * NF + wc * 32 + 2 * (lane & 3);
    float* orow1 = orow0 + 8 * NF;
    #pragma unroll
    for (int nb = 0; nb < 4; nb++) {
        *reinterpret_cast<float2*>(orow0 + nb * 8) = make_float2(acc[nb][0] * d0, acc[nb][1] * d0);
        *reinterpret_cast<float2*>(orow1 + nb * 8) = make_float2(acc[nb][2] * d1, acc[nb][3] * d1);
    }
}

// ---------------------------------------------------------------------------
extern "C" void kernel_launch(void* const* d_in, const int* in_sizes, int n_in,
                              void* d_out, int out_size) {
    const float* h   = (const float*)d_in[0];
    const int*   adj = (const int*)d_in[1];
    const float* W   = (const float*)d_in[2];
    const float* a   = (const float*)d_in[3];
    float* out = (float*)d_out;

    int sm1 = (32 * 128 + 128 * 128) * 4;
    cudaFuncSetAttribute(k_gemm1, cudaFuncAttributeMaxDynamicSharedMemorySize, sm1);
    cudaFuncSetAttribute(k_attn,  cudaFuncAttributeMaxDynamicSharedMemorySize, SMEM_TOT);

    k_pack<<<NN * (NN / 32) / 8, 256>>>(adj);
    k_gemm1<<<(NB * NN) / 32, 256, sm1>>>(h, W, a);
    k_attn<<<dim3(NN / RT, NB), 512, SMEM_TOT>>>(out);
}

// round 5
// speedup vs baseline: 2.3362x; 1.0590x over previous
#include <cuda_runtime.h>
#include <cuda_bf16.h>
#include <cstdint>

#define NB 4
#define NN 2048
#define NF 128
#define RT 64        // rows per attention block (M)
#define KT 64        // j per K tile
#define NTILE (NN / KT)

// ---- scratch (no cudaMalloc allowed) ----
__device__ __nv_bfloat16 g_WhT_h[NB * NF * NN];   // [b][o][n] hi
__device__ __nv_bfloat16 g_WhT_l[NB * NF * NN];   // [b][o][n] lo
__device__ float    g_f1[NB * NN];
__device__ float    g_f2[NB * NN];
__device__ uint32_t g_mask[NN * (NN / 32)];       // [row][64 words]

// ---------------------------------------------------------------------------
__device__ __forceinline__ uint32_t smem_u32(const void* p) {
    uint32_t a;
    asm("{ .reg .u64 t; cvta.to.shared.u64 t, %1; cvt.u32.u64 %0, t; }" : "=r"(a) : "l"(p));
    return a;
}
__device__ __forceinline__ uint32_t swz(uint32_t x) { return x ^ ((x >> 3) & 0x70); }

__device__ __forceinline__ uint32_t pk(float a, float b) {   // lo<-a, hi<-b
    uint32_t r;
    asm("cvt.rn.bf16x2.f32 %0, %1, %2;" : "=r"(r) : "f"(b), "f"(a));
    return r;
}
__device__ __forceinline__ void ldm4(uint32_t* r, uint32_t addr) {
    asm volatile("ldmatrix.sync.aligned.m8n8.x4.shared.b16 {%0,%1,%2,%3}, [%4];"
        : "=r"(r[0]), "=r"(r[1]), "=r"(r[2]), "=r"(r[3]) : "r"(addr));
}
__device__ __forceinline__ void mma16816(float* d, const uint32_t* a, const uint32_t* b) {
    asm volatile("mma.sync.aligned.m16n8k16.row.col.f32.bf16.bf16.f32 "
        "{%0,%1,%2,%3}, {%4,%5,%6,%7}, {%8,%9}, {%0,%1,%2,%3};"
        : "+f"(d[0]), "+f"(d[1]), "+f"(d[2]), "+f"(d[3])
        : "r"(a[0]), "r"(a[1]), "r"(a[2]), "r"(a[3]), "r"(b[0]), "r"(b[1]));
}
#define CPA(dst, src) asm volatile("cp.async.cg.shared.global [%0], [%1], 16;" :: "r"(dst), "l"(src) : "memory")
#define CPC()   asm volatile("cp.async.commit_group;" ::: "memory")
#define CPW(n)  asm volatile("cp.async.wait_group %0;" :: "n"(n) : "memory")

// ---------------------------------------------------------------------------
// Kernel 0: pack adjacency -> bitmask. One thread per output word (32 ints).
// ---------------------------------------------------------------------------
__global__ void k_pack(const int* __restrict__ adj) {
    int w = blockIdx.x * 256 + threadIdx.x;            // word index (131072 total)
    const int4* p = reinterpret_cast<const int4*>(adj) + (size_t)w * 8;
    uint32_t m = 0;
    #pragma unroll
    for (int k = 0; k < 8; k++) {
        int4 v = p[k];
        m |= (v.x > 0 ? 1u : 0u) << (4 * k);
        m |= (v.y > 0 ? 2u : 0u) << (4 * k);
        m |= (v.z > 0 ? 4u : 0u) << (4 * k);
        m |= (v.w > 0 ? 8u : 0u) << (4 * k);
    }
    g_mask[w] = m;
}

// ---------------------------------------------------------------------------
// Kernel 1: Wh = h@W ; f1 = Wh@a1 ; f2 = Wh@a2 ; WhT (bf16 hi/lo) to global
// ---------------------------------------------------------------------------
__global__ void k_gemm1(const float* __restrict__ h,
                        const float* __restrict__ W,
                        const float* __restrict__ a) {
    extern __shared__ float sm1[];
    float* hs = sm1;
    float* Ws = sm1 + 32 * 128;
    int tid = threadIdx.x;
    int m0 = blockIdx.x * 32;

    {
        const float4* src = reinterpret_cast<const float4*>(h + (size_t)m0 * NF);
        float4* dst = reinterpret_cast<float4*>(hs);
        #pragma unroll
        for (int it = 0; it < 4; it++) dst[tid + it * 256] = src[tid + it * 256];
    }
    {
        const float4* src = reinterpret_cast<const float4*>(W);
        float4* dst = reinterpret_cast<float4*>(Ws);
        #pragma unroll
        for (int it = 0; it < 16; it++) dst[tid + it * 256] = src[tid + it * 256];
    }
    __syncthreads();

    int ty = tid >> 5;
    int tx = tid & 31;
    float acc[4][4] = {};

    #pragma unroll 4
    for (int k = 0; k < 128; k++) {
        float4 bv = *reinterpret_cast<const float4*>(&Ws[k * 128 + tx * 4]);
        #pragma unroll
        for (int mi = 0; mi < 4; mi++) {
            float av = hs[(ty * 4 + mi) * 128 + k];
            acc[mi][0] += av * bv.x;
            acc[mi][1] += av * bv.y;
            acc[mi][2] += av * bv.z;
            acc[mi][3] += av * bv.w;
        }
    }

    float a1v[4], a2v[4];
    #pragma unroll
    for (int ni = 0; ni < 4; ni++) {
        a1v[ni] = a[tx * 4 + ni];
        a2v[ni] = a[NF + tx * 4 + ni];
    }
    #pragma unroll
    for (int mi = 0; mi < 4; mi++) {
        float p1 = acc[mi][0] * a1v[0] + acc[mi][1] * a1v[1]
                 + acc[mi][2] * a1v[2] + acc[mi][3] * a1v[3];
        float p2 = acc[mi][0] * a2v[0] + acc[mi][1] * a2v[1]
                 + acc[mi][2] * a2v[2] + acc[mi][3] * a2v[3];
        #pragma unroll
        for (int off = 16; off > 0; off >>= 1) {
            p1 += __shfl_xor_sync(0xffffffffu, p1, off);
            p2 += __shfl_xor_sync(0xffffffffu, p2, off);
        }
        if (tx == 0) {
            g_f1[m0 + ty * 4 + mi] = p1;
            g_f2[m0 + ty * 4 + mi] = p2;
        }
    }

    // transposed bf16 hi/lo: WhT[b][o][m]
    int bb = m0 >> 11;
    int ml = (m0 & 2047) + ty * 4;
    #pragma unroll
    for (int ni = 0; ni < 4; ni++) {
        int o = tx * 4 + ni;
        float v0 = acc[0][ni], v1 = acc[1][ni], v2 = acc[2][ni], v3 = acc[3][ni];
        uint32_t hA = pk(v0, v1);
        uint32_t hB = pk(v2, v3);
        float r0 = v0 - __uint_as_float(hA << 16);
        float r1 = v1 - __uint_as_float(hA & 0xffff0000u);
        float r2 = v2 - __uint_as_float(hB << 16);
        float r3 = v3 - __uint_as_float(hB & 0xffff0000u);
        size_t base = (size_t)(bb * 128 + o) * 1024 + (ml >> 1);
        uint32_t* dh = reinterpret_cast<uint32_t*>(g_WhT_h) + base;
        uint32_t* dl = reinterpret_cast<uint32_t*>(g_WhT_l) + base;
        dh[0] = hA; dh[1] = hB;
        dl[0] = pk(r0, r1); dl[1] = pk(r2, r3);
    }
}

// ---------------------------------------------------------------------------
// Kernel 2: fused masked-softmax attention + P@Wh via mma.sync (bf16 3-term)
// Software-pipelined: one barrier per tile; phaseA(t+1) overlaps MMA(t).
// ---------------------------------------------------------------------------
// smem byte offsets
#define AS_OFF 0u            // 2 bufs x (hi 8KB @0, lo 8KB @8192) = 32KB
#define BT_OFF 32768u        // 2 bufs x (hi 16KB + lo 16KB) = 64KB
#define F2_OFF 98304u        // 2048 floats
#define MS_OFF 106496u       // 64 rows x 64 words = 16KB
#define DI_OFF 122880u       // 64 floats
#define SMEM_TOT (122880 + 512)

// phase A for tile tt: P tile (bf16 hi/lo) into bufA[tt&1]; returns row-sum part
__device__ __forceinline__ float phase_a(int tt, char* smemA, float f1v, int r, int c8,
                                         const float* f2s, const uint32_t* ms,
                                         uint32_t aHiRel) {
    uint32_t mw = ms[r * 64 + tt * 2 + (c8 >> 5)];
    uint32_t bits = mw >> (c8 & 31);
    const float4* fv4 = reinterpret_cast<const float4*>(f2s + tt * KT + c8);
    float4 fa = fv4[0], fb = fv4[1];
    float s0 = f1v + fa.x; s0 = s0 > 0.f ? s0 : 0.2f * s0;
    float s1 = f1v + fa.y; s1 = s1 > 0.f ? s1 : 0.2f * s1;
    float s2 = f1v + fa.z; s2 = s2 > 0.f ? s2 : 0.2f * s2;
    float s3 = f1v + fa.w; s3 = s3 > 0.f ? s3 : 0.2f * s3;
    float p0 = (bits & 1u)   ? __expf(s0) : 0.0f;
    float p1 = (bits & 2u)   ? __expf(s1) : 0.0f;
    float p2 = (bits & 4u)   ? __expf(s2) : 0.0f;
    float p3 = (bits & 8u)   ? __expf(s3) : 0.0f;
    float s4 = f1v + fb.x; s4 = s4 > 0.f ? s4 : 0.2f * s4;
    float s5 = f1v + fb.y; s5 = s5 > 0.f ? s5 : 0.2f * s5;
    float s6 = f1v + fb.z; s6 = s6 > 0.f ? s6 : 0.2f * s6;
    float s7 = f1v + fb.w; s7 = s7 > 0.f ? s7 : 0.2f * s7;
    float p4 = (bits & 16u)  ? __expf(s4) : 0.0f;
    float p5 = (bits & 32u)  ? __expf(s5) : 0.0f;
    float p6 = (bits & 64u)  ? __expf(s6) : 0.0f;
    float p7 = (bits & 128u) ? __expf(s7) : 0.0f;
    uint32_t h0 = pk(p0, p1), h1 = pk(p2, p3), h2 = pk(p4, p5), h3 = pk(p6, p7);
    float q0 = p0 - __uint_as_float(h0 << 16);
    float q1 = p1 - __uint_as_float(h0 & 0xffff0000u);
    float q2 = p2 - __uint_as_float(h1 << 16);
    float q3 = p3 - __uint_as_float(h1 & 0xffff0000u);
    float q4 = p4 - __uint_as_float(h2 << 16);
    float q5 = p5 - __uint_as_float(h2 & 0xffff0000u);
    float q6 = p6 - __uint_as_float(h3 << 16);
    float q7 = p7 - __uint_as_float(h3 & 0xffff0000u);
    uint32_t off = AS_OFF + (uint32_t)(tt & 1) * 16384u + aHiRel;
    *reinterpret_cast<uint4*>(smemA + off)         = make_uint4(h0, h1, h2, h3);
    *reinterpret_cast<uint4*>(smemA + off + 8192u) =
        make_uint4(pk(q0, q1), pk(q2, q3), pk(q4, q5), pk(q6, q7));
    return ((p0 + p1) + (p2 + p3)) + ((p4 + p5) + (p6 + p7));
}

__global__ void __launch_bounds__(512, 1)
k_attn(float* __restrict__ out) {
    extern __shared__ char smemA[];
    uint32_t sb = smem_u32(smemA);
    int tid = threadIdx.x;
    int wid = tid >> 5;
    int lane = tid & 31;
    int b = blockIdx.y;
    int row0 = blockIdx.x * RT;

    float* f2s = reinterpret_cast<float*>(smemA + F2_OFF);
    uint32_t* ms = reinterpret_cast<uint32_t*>(smemA + MS_OFF);
    float* di = reinterpret_cast<float*>(smemA + DI_OFF);

    // ---- preload f2 (whole row, 8KB) and mask rows (16KB) ----
    {
        const float4* s4 = reinterpret_cast<const float4*>(g_f2 + b * NN);
        reinterpret_cast<float4*>(f2s)[tid] = s4[tid];
        const uint4* m4 = reinterpret_cast<const uint4*>(g_mask + row0 * 64);
        uint4* d4 = reinterpret_cast<uint4*>(ms);
        d4[tid * 2 + 0] = m4[tid * 2 + 0];
        d4[tid * 2 + 1] = m4[tid * 2 + 1];
    }

    // ---- per-thread phase-A constants ----
    int r = tid >> 3;                 // 0..63
    int c8 = (tid & 7) * 8;           // j offset within tile
    float f1v = g_f1[b * NN + row0 + r];
    uint32_t aHiRel = swz((uint32_t)(r * 128 + (tid & 7) * 16));

    // ---- MMA fragment addresses ----
    int wr = wid >> 2, wc = wid & 3;
    uint32_t aRowOff = (uint32_t)((wr * 16 + (lane & 7) + ((lane >> 3) & 1) * 8) * 128
                                  + (((lane >> 4) & 1) * 8) * 2);
    int bRow = wc * 32 + ((lane >> 4) & 1) * 8 + (lane & 7);
    uint32_t bColOff = (uint32_t)(((lane >> 3) & 1) * 16);
    uint32_t bBase = (uint32_t)(bRow * 128) + bColOff;

    // cp.async per-thread mapping (4 x 16B into one B buf)
    uint32_t cpDst[4];
    const __nv_bfloat16* cpSrcBase[4];
    #pragma unroll
    for (int k = 0; k < 4; k++) {
        int s = tid + k * 512;
        int split = s >> 10, s2 = s & 1023;
        int o = s2 >> 3, seg = s2 & 7;
        cpDst[k] = (uint32_t)split * 16384u + swz((uint32_t)(o * 128 + seg * 16));
        cpSrcBase[k] = (split ? g_WhT_l : g_WhT_h) + ((size_t)(b * 128 + o) * NN + seg * 8);
    }

    float acc[4][4] = {};
    float dacc = 0.0f;

    // prologue: issue B(0); then phaseA(0) (needs f2/ms -> barrier first)
    {
        uint32_t dbase = sb + BT_OFF;
        #pragma unroll
        for (int k = 0; k < 4; k++) CPA(dbase + cpDst[k], cpSrcBase[k]);
        CPC();
    }
    __syncthreads();                   // f2s/ms visible to all
    dacc += phase_a(0, smemA, f1v, r, c8, f2s, ms, aHiRel);

    for (int t = 0; t < NTILE; t++) {
        uint32_t bufB = sb + BT_OFF + (uint32_t)(t & 1) * 32768u;

        __syncthreads();  // phaseA(t) done everywhere; MMA(t-1) done everywhere

        if (t + 1 < NTILE) {
            uint32_t dbase = sb + BT_OFF + (uint32_t)((t + 1) & 1) * 32768u;
            #pragma unroll
            for (int k = 0; k < 4; k++) CPA(dbase + cpDst[k], cpSrcBase[k] + (t + 1) * KT);
            CPC();
            dacc += phase_a(t + 1, smemA, f1v, r, c8, f2s, ms, aHiRel);
            CPW(1);       // B(t) landed
        } else {
            CPW(0);
        }

        // ---- MMA(t): 4 ksteps x (3 terms x 4 nfrags) ----
        uint32_t bufA = sb + AS_OFF + (uint32_t)(t & 1) * 16384u;
        #pragma unroll
        for (int ks = 0; ks < 4; ks++) {
            uint32_t ah[4], al[4], bh[8], bl[8];
            uint32_t aAddr = bufA + swz(aRowOff + 32u * ks);
            ldm4(ah, aAddr);
            ldm4(al, aAddr + 8192u);
            uint32_t b0 = bufB + swz(bBase + 32u * ks);
            uint32_t b1 = bufB + swz(bBase + 2048u + 32u * ks);
            ldm4(bh + 0, b0);
            ldm4(bh + 4, b1);
            ldm4(bl + 0, b0 + 16384u);
            ldm4(bl + 4, b1 + 16384u);
            #pragma unroll
            for (int nb = 0; nb < 4; nb++) {
                mma16816(acc[nb], ah, bh + nb * 2);
                mma16816(acc[nb], ah, bl + nb * 2);
                mma16816(acc[nb], al, bh + nb * 2);
            }
        }
    }

    // ---- softmax denominator ----
    dacc += __shfl_xor_sync(0xffffffffu, dacc, 1);
    dacc += __shfl_xor_sync(0xffffffffu, dacc, 2);
    dacc += __shfl_xor_sync(0xffffffffu, dacc, 4);
    if ((lane & 7) == 0) di[wid * 4 + (lane >> 3)] = 1.0f / dacc;
    __syncthreads();

    // ---- epilogue: scale + store ----
    int rA = wr * 16 + (lane >> 2);
    float d0 = di[rA];
    float d1 = di[rA + 8];
    float* orow0 = out + ((size_t)(b * NN + row0 + rA)) * NF + wc * 32 + 2 * (lane & 3);
    float* orow1 = orow0 + 8 * NF;
    #pragma unroll
    for (int nb = 0; nb < 4; nb++) {
        *reinterpret_cast<float2*>(orow0 + nb * 8) = make_float2(acc[nb][0] * d0, acc[nb][1] * d0);
        *reinterpret_cast<float2*>(orow1 + nb * 8) = make_float2(acc[nb][2] * d1, acc[nb][3] * d1);
    }
}

// ---------------------------------------------------------------------------
extern "C" void kernel_launch(void* const* d_in, const int* in_sizes, int n_in,
                              void* d_out, int out_size) {
    const float* h   = (const float*)d_in[0];
    const int*   adj = (const int*)d_in[1];
    const float* W   = (const float*)d_in[2];
    const float* a   = (const float*)d_in[3];
    float* out = (float*)d_out;

    int sm1 = (32 * 128 + 128 * 128) * 4;
    cudaFuncSetAttribute(k_gemm1, cudaFuncAttributeMaxDynamicSharedMemorySize, sm1);
    cudaFuncSetAttribute(k_attn,  cudaFuncAttributeMaxDynamicSharedMemorySize, SMEM_TOT);

    k_pack<<<NN * (NN / 32) / 256, 256>>>(adj);
    k_gemm1<<<(NB * NN) / 32, 256, sm1>>>(h, W, a);
    k_attn<<<dim3(NN / RT, NB), 512, SMEM_TOT>>>(out);
}

// round 6
// speedup vs baseline: 2.5018x; 1.0709x over previous
#include <cuda_runtime.h>
#include <cuda_fp16.h>
#include <cuda_bf16.h>
#include <cstdint>

#define NB 4
#define NN 2048
#define NF 128
#define RT 64        // rows per attention block (M)
#define KT 64        // j per K tile
#define NTILE (NN / KT)
#define SHIFT 4.0f

// ---- scratch (no cudaMalloc allowed) ----
__device__ __half g_WhT_h[NB * NF * NN];   // [b][o][n] fp16 hi
__device__ __half g_WhT_l[NB * NF * NN];   // [b][o][n] fp16 lo
__device__ float    g_f1[NB * NN];
__device__ float    g_f2[NB * NN];
__device__ uint32_t g_mask[NN * (NN / 32)];

// ---------------------------------------------------------------------------
__device__ __forceinline__ uint32_t smem_u32(const void* p) {
    uint32_t a;
    asm("{ .reg .u64 t; cvta.to.shared.u64 t, %1; cvt.u32.u64 %0, t; }" : "=r"(a) : "l"(p));
    return a;
}
__device__ __forceinline__ uint32_t swz(uint32_t x) { return x ^ ((x >> 3) & 0x70); }

__device__ __forceinline__ uint32_t pkh(float a, float b) {   // fp16x2: lo<-a, hi<-b
    uint32_t r;
    asm("cvt.rn.f16x2.f32 %0, %1, %2;" : "=r"(r) : "f"(b), "f"(a));
    return r;
}
__device__ __forceinline__ void ldm4(uint32_t* r, uint32_t addr) {
    asm volatile("ldmatrix.sync.aligned.m8n8.x4.shared.b16 {%0,%1,%2,%3}, [%4];"
        : "=r"(r[0]), "=r"(r[1]), "=r"(r[2]), "=r"(r[3]) : "r"(addr));
}
__device__ __forceinline__ void mma16816(float* d, const uint32_t* a, const uint32_t* b) {
    asm volatile("mma.sync.aligned.m16n8k16.row.col.f32.f16.f16.f32 "
        "{%0,%1,%2,%3}, {%4,%5,%6,%7}, {%8,%9}, {%0,%1,%2,%3};"
        : "+f"(d[0]), "+f"(d[1]), "+f"(d[2]), "+f"(d[3])
        : "r"(a[0]), "r"(a[1]), "r"(a[2]), "r"(a[3]), "r"(b[0]), "r"(b[1]));
}
#define CPA(dst, src) asm volatile("cp.async.cg.shared.global [%0], [%1], 16;" :: "r"(dst), "l"(src) : "memory")
#define CPC()   asm volatile("cp.async.commit_group;" ::: "memory")
#define CPW(n)  asm volatile("cp.async.wait_group %0;" :: "n"(n) : "memory")

// ---------------------------------------------------------------------------
// Kernel 0: pack adjacency -> bitmask. One thread per output word (32 ints).
// ---------------------------------------------------------------------------
__global__ void k_pack(const int* __restrict__ adj) {
    int w = blockIdx.x * 128 + threadIdx.x;            // word index (131072 total)
    const int4* p = reinterpret_cast<const int4*>(adj) + (size_t)w * 8;
    uint32_t m = 0;
    #pragma unroll
    for (int k = 0; k < 8; k++) {
        int4 v = p[k];
        m |= (v.x > 0 ? 1u : 0u) << (4 * k);
        m |= (v.y > 0 ? 2u : 0u) << (4 * k);
        m |= (v.z > 0 ? 4u : 0u) << (4 * k);
        m |= (v.w > 0 ? 8u : 0u) << (4 * k);
    }
    g_mask[w] = m;
}

// ---------------------------------------------------------------------------
// Kernel 1: Wh = h@W (fp32) ; f1/f2 ; WhT (fp16 hi/lo) to global
// ---------------------------------------------------------------------------
__global__ void k_gemm1(const float* __restrict__ h,
                        const float* __restrict__ W,
                        const float* __restrict__ a) {
    extern __shared__ float sm1[];
    float* hs = sm1;
    float* Ws = sm1 + 32 * 128;
    int tid = threadIdx.x;
    int m0 = blockIdx.x * 32;

    {
        const float4* src = reinterpret_cast<const float4*>(h + (size_t)m0 * NF);
        float4* dst = reinterpret_cast<float4*>(hs);
        #pragma unroll
        for (int it = 0; it < 4; it++) dst[tid + it * 256] = src[tid + it * 256];
    }
    {
        const float4* src = reinterpret_cast<const float4*>(W);
        float4* dst = reinterpret_cast<float4*>(Ws);
        #pragma unroll
        for (int it = 0; it < 16; it++) dst[tid + it * 256] = src[tid + it * 256];
    }
    __syncthreads();

    int ty = tid >> 5;
    int tx = tid & 31;
    float acc[4][4] = {};

    #pragma unroll 4
    for (int k = 0; k < 128; k++) {
        float4 bv = *reinterpret_cast<const float4*>(&Ws[k * 128 + tx * 4]);
        #pragma unroll
        for (int mi = 0; mi < 4; mi++) {
            float av = hs[(ty * 4 + mi) * 128 + k];
            acc[mi][0] += av * bv.x;
            acc[mi][1] += av * bv.y;
            acc[mi][2] += av * bv.z;
            acc[mi][3] += av * bv.w;
        }
    }

    float a1v[4], a2v[4];
    #pragma unroll
    for (int ni = 0; ni < 4; ni++) {
        a1v[ni] = a[tx * 4 + ni];
        a2v[ni] = a[NF + tx * 4 + ni];
    }
    #pragma unroll
    for (int mi = 0; mi < 4; mi++) {
        float p1 = acc[mi][0] * a1v[0] + acc[mi][1] * a1v[1]
                 + acc[mi][2] * a1v[2] + acc[mi][3] * a1v[3];
        float p2 = acc[mi][0] * a2v[0] + acc[mi][1] * a2v[1]
                 + acc[mi][2] * a2v[2] + acc[mi][3] * a2v[3];
        #pragma unroll
        for (int off = 16; off > 0; off >>= 1) {
            p1 += __shfl_xor_sync(0xffffffffu, p1, off);
            p2 += __shfl_xor_sync(0xffffffffu, p2, off);
        }
        if (tx == 0) {
            g_f1[m0 + ty * 4 + mi] = p1;
            g_f2[m0 + ty * 4 + mi] = p2;
        }
    }

    // transposed fp16 hi/lo: WhT[b][o][m]
    int bb = m0 >> 11;
    int ml = (m0 & 2047) + ty * 4;
    #pragma unroll
    for (int ni = 0; ni < 4; ni++) {
        int o = tx * 4 + ni;
        float v0 = acc[0][ni], v1 = acc[1][ni], v2 = acc[2][ni], v3 = acc[3][ni];
        uint32_t hA = pkh(v0, v1);
        uint32_t hB = pkh(v2, v3);
        float2 fA = __half22float2(*reinterpret_cast<__half2*>(&hA));
        float2 fB = __half22float2(*reinterpret_cast<__half2*>(&hB));
        float r0 = v0 - fA.x, r1 = v1 - fA.y;
        float r2 = v2 - fB.x, r3 = v3 - fB.y;
        size_t base = (size_t)(bb * 128 + o) * 1024 + (ml >> 1);
        uint32_t* dh = reinterpret_cast<uint32_t*>(g_WhT_h) + base;
        uint32_t* dl = reinterpret_cast<uint32_t*>(g_WhT_l) + base;
        dh[0] = hA; dh[1] = hB;
        dl[0] = pkh(r0, r1); dl[1] = pkh(r2, r3);
    }
}

// ---------------------------------------------------------------------------
// Kernel 2: fused masked-softmax attention + P@Wh via mma.sync (2-term fp16)
// ---------------------------------------------------------------------------
// smem byte offsets
#define AS_OFF 0u            // 2 bufs x 8KB (fp16 P tile)
#define BT_OFF 16384u        // 2 bufs x (hi 16KB + lo 16KB) = 64KB
#define F2_OFF 81920u        // 2048 floats
#define MS_OFF 90112u        // 64 rows x 64 words = 16KB
#define DI_OFF 106496u       // 64 floats
#define SMEM_TOT (106496 + 512)

// phase A for tile tt: P tile (fp16) into bufA[tt&1]; returns row-sum part
__device__ __forceinline__ float phase_a(int tt, char* smemA, float f1v, int r, int c8,
                                         const float* f2s, const uint32_t* ms,
                                         uint32_t aHiRel) {
    uint32_t mw = ms[r * 64 + tt * 2 + (c8 >> 5)];
    uint32_t bits = mw >> (c8 & 31);
    const float4* fv4 = reinterpret_cast<const float4*>(f2s + tt * KT + c8);
    float4 fa = fv4[0], fb = fv4[1];
    float s0 = f1v + fa.x; s0 = s0 > 0.f ? s0 : 0.2f * s0;
    float s1 = f1v + fa.y; s1 = s1 > 0.f ? s1 : 0.2f * s1;
    float s2 = f1v + fa.z; s2 = s2 > 0.f ? s2 : 0.2f * s2;
    float s3 = f1v + fa.w; s3 = s3 > 0.f ? s3 : 0.2f * s3;
    float p0 = (bits & 1u)   ? __expf(s0 - SHIFT) : 0.0f;
    float p1 = (bits & 2u)   ? __expf(s1 - SHIFT) : 0.0f;
    float p2 = (bits & 4u)   ? __expf(s2 - SHIFT) : 0.0f;
    float p3 = (bits & 8u)   ? __expf(s3 - SHIFT) : 0.0f;
    float s4 = f1v + fb.x; s4 = s4 > 0.f ? s4 : 0.2f * s4;
    float s5 = f1v + fb.y; s5 = s5 > 0.f ? s5 : 0.2f * s5;
    float s6 = f1v + fb.z; s6 = s6 > 0.f ? s6 : 0.2f * s6;
    float s7 = f1v + fb.w; s7 = s7 > 0.f ? s7 : 0.2f * s7;
    float p4 = (bits & 16u)  ? __expf(s4 - SHIFT) : 0.0f;
    float p5 = (bits & 32u)  ? __expf(s5 - SHIFT) : 0.0f;
    float p6 = (bits & 64u)  ? __expf(s6 - SHIFT) : 0.0f;
    float p7 = (bits & 128u) ? __expf(s7 - SHIFT) : 0.0f;
    uint32_t off = AS_OFF + (uint32_t)(tt & 1) * 8192u + aHiRel;
    *reinterpret_cast<uint4*>(smemA + off) =
        make_uint4(pkh(p0, p1), pkh(p2, p3), pkh(p4, p5), pkh(p6, p7));
    return ((p0 + p1) + (p2 + p3)) + ((p4 + p5) + (p6 + p7));
}

__global__ void __launch_bounds__(512, 1)
k_attn(float* __restrict__ out) {
    extern __shared__ char smemA[];
    uint32_t sb = smem_u32(smemA);
    int tid = threadIdx.x;
    int wid = tid >> 5;
    int lane = tid & 31;
    int b = blockIdx.y;
    int row0 = blockIdx.x * RT;

    float* f2s = reinterpret_cast<float*>(smemA + F2_OFF);
    uint32_t* ms = reinterpret_cast<uint32_t*>(smemA + MS_OFF);
    float* di = reinterpret_cast<float*>(smemA + DI_OFF);

    // ---- preload f2 row (8KB) and mask rows (16KB) ----
    {
        const float4* s4 = reinterpret_cast<const float4*>(g_f2 + b * NN);
        reinterpret_cast<float4*>(f2s)[tid] = s4[tid];
        const uint4* m4 = reinterpret_cast<const uint4*>(g_mask + row0 * 64);
        uint4* d4 = reinterpret_cast<uint4*>(ms);
        d4[tid * 2 + 0] = m4[tid * 2 + 0];
        d4[tid * 2 + 1] = m4[tid * 2 + 1];
    }

    // ---- per-thread phase-A constants ----
    int r = tid >> 3;
    int c8 = (tid & 7) * 8;
    float f1v = g_f1[b * NN + row0 + r];
    uint32_t aHiRel = swz((uint32_t)(r * 128 + (tid & 7) * 16));

    // ---- MMA fragment addresses ----
    int wr = wid >> 2, wc = wid & 3;
    uint32_t aRowOff = (uint32_t)((wr * 16 + (lane & 7) + ((lane >> 3) & 1) * 8) * 128
                                  + (((lane >> 4) & 1) * 8) * 2);
    int bRow = wc * 32 + ((lane >> 4) & 1) * 8 + (lane & 7);
    uint32_t bColOff = (uint32_t)(((lane >> 3) & 1) * 16);
    uint32_t bBase = (uint32_t)(bRow * 128) + bColOff;

    // cp.async per-thread mapping (4 x 16B into one B buf)
    uint32_t cpDst[4];
    const __half* cpSrcBase[4];
    #pragma unroll
    for (int k = 0; k < 4; k++) {
        int s = tid + k * 512;
        int split = s >> 10, s2 = s & 1023;
        int o = s2 >> 3, seg = s2 & 7;
        cpDst[k] = (uint32_t)split * 16384u + swz((uint32_t)(o * 128 + seg * 16));
        cpSrcBase[k] = (split ? g_WhT_l : g_WhT_h) + ((size_t)(b * 128 + o) * NN + seg * 8);
    }

    float acc[4][4] = {};
    float dacc = 0.0f;

    // prologue
    {
        uint32_t dbase = sb + BT_OFF;
        #pragma unroll
        for (int k = 0; k < 4; k++) CPA(dbase + cpDst[k], cpSrcBase[k]);
        CPC();
    }
    __syncthreads();
    dacc += phase_a(0, smemA, f1v, r, c8, f2s, ms, aHiRel);

    for (int t = 0; t < NTILE; t++) {
        uint32_t bufB = sb + BT_OFF + (uint32_t)(t & 1) * 32768u;

        __syncthreads();   // phaseA(t) + MMA(t-1) complete everywhere

        if (t + 1 < NTILE) {
            uint32_t dbase = sb + BT_OFF + (uint32_t)((t + 1) & 1) * 32768u;
            #pragma unroll
            for (int k = 0; k < 4; k++) CPA(dbase + cpDst[k], cpSrcBase[k] + (t + 1) * KT);
            CPC();
            dacc += phase_a(t + 1, smemA, f1v, r, c8, f2s, ms, aHiRel);
            CPW(1);
        } else {
            CPW(0);
        }

        // ---- MMA(t): 4 ksteps x (2 terms x 4 nfrags) ----
        uint32_t bufA = sb + AS_OFF + (uint32_t)(t & 1) * 8192u;
        #pragma unroll
        for (int ks = 0; ks < 4; ks++) {
            uint32_t ah[4], bh[8], bl[8];
            ldm4(ah, bufA + swz(aRowOff + 32u * ks));
            uint32_t b0 = bufB + swz(bBase + 32u * ks);
            uint32_t b1 = bufB + swz(bBase + 2048u + 32u * ks);
            ldm4(bh + 0, b0);
            ldm4(bh + 4, b1);
            ldm4(bl + 0, b0 + 16384u);
            ldm4(bl + 4, b1 + 16384u);
            #pragma unroll
            for (int nb = 0; nb < 4; nb++) {
                mma16816(acc[nb], ah, bh + nb * 2);
                mma16816(acc[nb], ah, bl + nb * 2);
            }
        }
    }

    // ---- softmax denominator ----
    dacc += __shfl_xor_sync(0xffffffffu, dacc, 1);
    dacc += __shfl_xor_sync(0xffffffffu, dacc, 2);
    dacc += __shfl_xor_sync(0xffffffffu, dacc, 4);
    if ((lane & 7) == 0) di[wid * 4 + (lane >> 3)] = 1.0f / dacc;
    __syncthreads();

    // ---- epilogue: scale + store ----
    int rA = wr * 16 + (lane >> 2);
    float d0 = di[rA];
    float d1 = di[rA + 8];
    float* orow0 = out + ((size_t)(b * NN + row0 + rA)) * NF + wc * 32 + 2 * (lane & 3);
    float* orow1 = orow0 + 8 * NF;
    #pragma unroll
    for (int nb = 0; nb < 4; nb++) {
        *reinterpret_cast<float2*>(orow0 + nb * 8) = make_float2(acc[nb][0] * d0, acc[nb][1] * d0);
        *reinterpret_cast<float2*>(orow1 + nb * 8) = make_float2(acc[nb][2] * d1, acc[nb][3] * d1);
    }
}

// ---------------------------------------------------------------------------
extern "C" void kernel_launch(void* const* d_in, const int* in_sizes, int n_in,
                              void* d_out, int out_size) {
    const float* h   = (const float*)d_in[0];
    const int*   adj = (const int*)d_in[1];
    const float* W   = (const float*)d_in[2];
    const float* a   = (const float*)d_in[3];
    float* out = (float*)d_out;

    int sm1 = (32 * 128 + 128 * 128) * 4;
    cudaFuncSetAttribute(k_gemm1, cudaFuncAttributeMaxDynamicSharedMemorySize, sm1);
    cudaFuncSetAttribute(k_attn,  cudaFuncAttributeMaxDynamicSharedMemorySize, SMEM_TOT);

    k_pack<<<NN * (NN / 32) / 128, 128>>>(adj);
    k_gemm1<<<(NB * NN) / 32, 256, sm1>>>(h, W, a);
    k_attn<<<dim3(NN / RT, NB), 512, SMEM_TOT>>>(out);
}